// round 1
// baseline (speedup 1.0000x reference)
#include <cuda_runtime.h>
#include <math.h>

#define E_DIM 256
#define N_MAX 8192
#define TILE 128
#define BK 16

// ---------------- device scratch (no allocations allowed) ----------------
__device__ float  g_xn[N_MAX * E_DIM];   // normalized rows
__device__ int    g_target[N_MAX];       // normalized int32 targets
__device__ float  g_invcnt[4];
__device__ float  g_wbase;
__device__ int    g_last;
__device__ double g_sum;

// ---------------- setup: dtype detect + histogram + constants ----------------
__global__ void setup_kernel(const int* __restrict__ traw, int n) {
    __shared__ int s_cnt[4];
    __shared__ int s_flag;   // 1 if any odd word nonzero -> int32 data
    int tid = threadIdx.x;
    if (tid < 4) s_cnt[tid] = 0;
    if (tid == 0) s_flag = 0;
    __syncthreads();

    // scan odd 32-bit words among the first n words (safe for both dtypes)
    int f = 0;
    for (int i = 2 * tid + 1; i < n; i += 2 * blockDim.x)
        if (traw[i] != 0) f = 1;
    if (f) atomicOr(&s_flag, 1);
    __syncthreads();
    int is64 = (s_flag == 0);

    for (int i = tid; i < n; i += blockDim.x) {
        int t = is64 ? traw[2 * i] : traw[i];
        g_target[i] = t;
        atomicAdd(&s_cnt[t & 3], 1);
    }
    __syncthreads();
    if (tid == 0) {
        float wb = 0.f;
        int L = 0;
        for (int c = 0; c < 4; c++) {
            float ic = (s_cnt[c] > 0) ? (1.0f / (float)s_cnt[c]) : 0.0f;
            g_invcnt[c] = ic;
            if (s_cnt[c] > 0) { wb += ic; L = c; }
        }
        g_wbase = wb;
        g_last = L;
        g_sum = 0.0;   // zero accumulator every launch (graph replays)
    }
}

// ---------------- row normalize: one block (256 threads) per row ----------------
__global__ void normalize_kernel(const float* __restrict__ x) {
    int row = blockIdx.x;
    int t = threadIdx.x;
    float v = x[row * E_DIM + t];
    float s = v * v;
    #pragma unroll
    for (int o = 16; o > 0; o >>= 1) s += __shfl_xor_sync(0xffffffffu, s, o);
    __shared__ float ws[8];
    __shared__ float s_inv;
    if ((t & 31) == 0) ws[t >> 5] = s;
    __syncthreads();
    if (t == 0) {
        float z = 0.f;
        #pragma unroll
        for (int i = 0; i < 8; i++) z += ws[i];
        s_inv = 1.0f / fmaxf(sqrtf(z), 1e-8f);
    }
    __syncthreads();
    g_xn[row * E_DIM + t] = v * s_inv;
}

// ---------------- pair kernel: 128x128 tiles over strict upper triangle ----------------
__global__ __launch_bounds__(256) void pair_kernel(int nTiles) {
    // map linear block id -> (bi, bj) with bj >= bi
    int idx = blockIdx.x;
    int bi = 0;
    while (idx >= nTiles - bi) { idx -= nTiles - bi; bi++; }
    int bj = bi + idx;
    const int row0 = bi * TILE;
    const int col0 = bj * TILE;

    __shared__ float As[BK][TILE + 4];
    __shared__ float Bs[BK][TILE + 4];
    __shared__ int   tA[TILE];
    __shared__ int   tB[TILE];
    __shared__ float sIC[4];
    __shared__ float red[256];

    const int tid = threadIdx.x;
    if (tid < 4) sIC[tid] = g_invcnt[tid];
    if (tid < TILE) { tA[tid] = g_target[row0 + tid]; tB[tid] = g_target[col0 + tid]; }
    const float wbase = g_wbase;
    const int L = g_last;

    float acc[8][8];
    #pragma unroll
    for (int i = 0; i < 8; i++)
        #pragma unroll
        for (int j = 0; j < 8; j++) acc[i][j] = 0.f;

    const int lr = tid >> 1;            // 0..127 (tile row/col it loads)
    const int lk = (tid & 1) * 8;       // 0 or 8 (k offset)
    const float* Aptr = g_xn + (size_t)(row0 + lr) * E_DIM + lk;
    const float* Bptr = g_xn + (size_t)(col0 + lr) * E_DIM + lk;

    const int ty = tid >> 4;            // 0..15
    const int tx = tid & 15;            // 0..15

    for (int k0 = 0; k0 < E_DIM; k0 += BK) {
        __syncthreads();
        float4 a0 = *(const float4*)(Aptr + k0);
        float4 a1 = *(const float4*)(Aptr + k0 + 4);
        float4 b0 = *(const float4*)(Bptr + k0);
        float4 b1 = *(const float4*)(Bptr + k0 + 4);
        As[lk + 0][lr] = a0.x; As[lk + 1][lr] = a0.y; As[lk + 2][lr] = a0.z; As[lk + 3][lr] = a0.w;
        As[lk + 4][lr] = a1.x; As[lk + 5][lr] = a1.y; As[lk + 6][lr] = a1.z; As[lk + 7][lr] = a1.w;
        Bs[lk + 0][lr] = b0.x; Bs[lk + 1][lr] = b0.y; Bs[lk + 2][lr] = b0.z; Bs[lk + 3][lr] = b0.w;
        Bs[lk + 4][lr] = b1.x; Bs[lk + 5][lr] = b1.y; Bs[lk + 6][lr] = b1.z; Bs[lk + 7][lr] = b1.w;
        __syncthreads();

        #pragma unroll
        for (int kk = 0; kk < BK; kk++) {
            float4 av0 = *(const float4*)&As[kk][ty * 8];
            float4 av1 = *(const float4*)&As[kk][ty * 8 + 4];
            float4 bv0 = *(const float4*)&Bs[kk][tx * 8];
            float4 bv1 = *(const float4*)&Bs[kk][tx * 8 + 4];
            float a[8] = {av0.x, av0.y, av0.z, av0.w, av1.x, av1.y, av1.z, av1.w};
            float b[8] = {bv0.x, bv0.y, bv0.z, bv0.w, bv1.x, bv1.y, bv1.z, bv1.w};
            #pragma unroll
            for (int i = 0; i < 8; i++)
                #pragma unroll
                for (int j = 0; j < 8; j++)
                    acc[i][j] = fmaf(a[i], b[j], acc[i][j]);
        }
    }

    // fused epilogue: loss terms for this tile
    float local = 0.f;
    #pragma unroll
    for (int i = 0; i < 8; i++) {
        const int ri = ty * 8 + i;
        const int gi = row0 + ri;
        const int ta = tA[ri];
        const float ica = sIC[ta];
        const bool aL = (ta == L);
        #pragma unroll
        for (int j = 0; j < 8; j++) {
            const int cj = tx * 8 + j;
            const int gj = col0 + cj;
            if (gj > gi) {
                const float cs = acc[i][j];
                const int tb = tB[cj];
                const float w = (ta == tb) ? wbase : (wbase - ica - sIC[tb]);
                local += w * (1.0f - cs);
                if (aL != (tb == L)) local += fmaxf(cs - 0.5f, 0.0f);
            }
        }
    }

    red[tid] = local;
    __syncthreads();
    #pragma unroll
    for (int s = 128; s > 0; s >>= 1) {
        if (tid < s) red[tid] += red[tid + s];
        __syncthreads();
    }
    if (tid == 0) atomicAdd(&g_sum, (double)red[0]);
}

// ---------------- finalize ----------------
__global__ void finalize_kernel(float* out, double invN) {
    out[0] = (float)(g_sum * invN);
}

extern "C" void kernel_launch(void* const* d_in, const int* in_sizes, int n_in,
                              void* d_out, int out_size) {
    const float* x = (const float*)d_in[0];
    const int* traw = (const int*)d_in[1];   // int32 view; setup detects int64 vs int32
    float* out = (float*)d_out;

    const int n = in_sizes[1];               // number of rows (8192)
    const int nTiles = n / TILE;             // 64
    const int nBlocks = nTiles * (nTiles + 1) / 2;  // 2080

    setup_kernel<<<1, 256>>>(traw, n);
    normalize_kernel<<<n, E_DIM>>>(x);
    pair_kernel<<<nBlocks, 256>>>(nTiles);
    finalize_kernel<<<1, 1>>>(out, 1.0 / (double)n);
}

// round 5
// speedup vs baseline: 2.4847x; 2.4847x over previous
#include <cuda_runtime.h>
#include <cuda_bf16.h>
#include <math.h>
#include <stdint.h>

#define E_DIM 256
#define N_MAX 8192
#define TILE 128
#define SA 264            // padded smem row stride in bf16 (528B)

// ---------------- device scratch ----------------
__device__ __nv_bfloat16 g_xb[N_MAX * E_DIM];
__device__ int    g_target[N_MAX];
__device__ float  g_invcnt[4];
__device__ float  g_wbase;
__device__ int    g_last;
__device__ double g_sum;

// ---------------- helpers ----------------
__device__ __forceinline__ uint32_t smem_u32(const void* p) {
    uint32_t a;
    asm("{ .reg .u64 t; cvta.to.shared.u64 t, %1; cvt.u32.u64 %0, t; }" : "=r"(a) : "l"(p));
    return a;
}
__device__ __forceinline__ void cp_async16(uint32_t dst, const void* src) {
    asm volatile("cp.async.cg.shared.global [%0], [%1], 16;" :: "r"(dst), "l"(src) : "memory");
}
__device__ __forceinline__ void cp_async_wait_all() {
    asm volatile("cp.async.commit_group;\ncp.async.wait_group 0;" ::: "memory");
}
__device__ __forceinline__ void ldsm_x4(uint32_t* r, uint32_t addr) {
    asm volatile("ldmatrix.sync.aligned.m8n8.x4.shared.b16 {%0,%1,%2,%3}, [%4];"
                 : "=r"(r[0]), "=r"(r[1]), "=r"(r[2]), "=r"(r[3]) : "r"(addr));
}
__device__ __forceinline__ void mma_16816(float* d, const uint32_t* a, const uint32_t* b) {
    asm volatile(
        "mma.sync.aligned.m16n8k16.row.col.f32.bf16.bf16.f32 "
        "{%0,%1,%2,%3}, {%4,%5,%6,%7}, {%8,%9}, {%0,%1,%2,%3};"
        : "+f"(d[0]), "+f"(d[1]), "+f"(d[2]), "+f"(d[3])
        : "r"(a[0]), "r"(a[1]), "r"(a[2]), "r"(a[3]), "r"(b[0]), "r"(b[1]));
}

// ---------------- setup ----------------
__global__ void setup_kernel(const int* __restrict__ traw, int n) {
    __shared__ int s_cnt[4];
    __shared__ int s_flag;
    int tid = threadIdx.x;
    if (tid < 4) s_cnt[tid] = 0;
    if (tid == 0) s_flag = 0;
    __syncthreads();
    int f = 0;
    for (int i = 2 * tid + 1; i < n; i += 2 * blockDim.x)
        if (traw[i] != 0) f = 1;
    if (f) atomicOr(&s_flag, 1);
    __syncthreads();
    int is64 = (s_flag == 0);
    for (int i = tid; i < n; i += blockDim.x) {
        int t = is64 ? traw[2 * i] : traw[i];
        g_target[i] = t;
        atomicAdd(&s_cnt[t & 3], 1);
    }
    __syncthreads();
    if (tid == 0) {
        float wb = 0.f;
        int L = 0;
        for (int c = 0; c < 4; c++) {
            float ic = (s_cnt[c] > 0) ? (1.0f / (float)s_cnt[c]) : 0.0f;
            g_invcnt[c] = ic;
            if (s_cnt[c] > 0) { wb += ic; L = c; }
        }
        g_wbase = wb;
        g_last = L;
        g_sum = 0.0;
    }
}

// ---------------- normalize + bf16 convert ----------------
__global__ void normalize_kernel(const float* __restrict__ x) {
    int row = blockIdx.x;
    int t = threadIdx.x;
    float v = x[row * E_DIM + t];
    float s = v * v;
    #pragma unroll
    for (int o = 16; o > 0; o >>= 1) s += __shfl_xor_sync(0xffffffffu, s, o);
    __shared__ float ws[8];
    __shared__ float s_inv;
    if ((t & 31) == 0) ws[t >> 5] = s;
    __syncthreads();
    if (t == 0) {
        float z = 0.f;
        #pragma unroll
        for (int i = 0; i < 8; i++) z += ws[i];
        s_inv = 1.0f / fmaxf(sqrtf(z), 1e-8f);
    }
    __syncthreads();
    g_xb[row * E_DIM + t] = __float2bfloat16(v * s_inv);
}

// ---------------- pair kernel: mma.sync over upper-tri 128x128 tiles ----------------
#define OFF_TA   0
#define OFF_TB   512
#define OFF_RED  1024
#define OFF_A    1536
#define OFF_B    (1536 + 128 * SA * 2)
#define SMEM_TOTAL (1536 + 2 * 128 * SA * 2)

__global__ __launch_bounds__(256, 1) void pair_kernel(int nTiles) {
    extern __shared__ char smem[];
    const uint32_t sbase = smem_u32(smem);
    const int tid = threadIdx.x;
    const int wid = tid >> 5;
    const int lid = tid & 31;

    // block -> (bi, bj), bj >= bi
    int idx = blockIdx.x;
    int bi = 0;
    while (idx >= nTiles - bi) { idx -= nTiles - bi; bi++; }
    const int bj = bi + idx;
    const int row0 = bi * TILE;
    const int col0 = bj * TILE;

    // async tile loads: 128 rows x 256 bf16 each, as 16B vectors (32 per row)
    {
        const uint4* __restrict__ srcA = (const uint4*)(g_xb + (size_t)row0 * E_DIM);
        const uint4* __restrict__ srcB = (const uint4*)(g_xb + (size_t)col0 * E_DIM);
        #pragma unroll 4
        for (int v = tid; v < 4096; v += 256) {
            int row = v >> 5;
            int c8 = (v & 31) << 3;
            uint32_t d = (uint32_t)(row * SA + c8) * 2u;
            cp_async16(sbase + OFF_A + d, srcA + v);
            cp_async16(sbase + OFF_B + d, srcB + v);
        }
    }
    int* tA = (int*)(smem + OFF_TA);
    int* tB = (int*)(smem + OFF_TB);
    if (tid < TILE) { tA[tid] = g_target[row0 + tid]; tB[tid] = g_target[col0 + tid]; }
    cp_async_wait_all();
    __syncthreads();

    // warp decomposition: wm in {0,1} -> 64 rows, wn in {0..3} -> 32 cols
    const int wm = wid & 1;
    const int wn = wid >> 1;
    const int rbase = wm * 64;
    const int cbase = wn * 32;

    float acc[4][4][4];
    #pragma unroll
    for (int mt = 0; mt < 4; mt++)
        #pragma unroll
        for (int nt = 0; nt < 4; nt++)
            #pragma unroll
            for (int q = 0; q < 4; q++) acc[mt][nt][q] = 0.f;

    const int mi = lid >> 3;     // ldmatrix matrix index 0..3
    const int mr = lid & 7;      // row within 8x8 matrix
    // A x4: m0 rows+0 k+0 | m1 rows+8 k+0 | m2 rows+0 k+8 | m3 rows+8 k+8
    const uint32_t aAddrBase = sbase + OFF_A
        + (uint32_t)((rbase + mr + (mi & 1) * 8) * SA + (mi >> 1) * 8) * 2u;
    // B x4: m0 n+0 k+0 | m1 n+0 k+8 | m2 n+8 k+0 | m3 n+8 k+8
    const uint32_t bAddrBase = sbase + OFF_B
        + (uint32_t)((cbase + mr + (mi >> 1) * 8) * SA + (mi & 1) * 8) * 2u;

    #pragma unroll 4
    for (int k = 0; k < E_DIM; k += 16) {
        uint32_t af[4][4];
        uint32_t bf[4][2];
        #pragma unroll
        for (int mt = 0; mt < 4; mt++)
            ldsm_x4(af[mt], aAddrBase + (uint32_t)(mt * 16 * SA + k) * 2u);
        #pragma unroll
        for (int bt = 0; bt < 2; bt++) {
            uint32_t r[4];
            ldsm_x4(r, bAddrBase + (uint32_t)(bt * 16 * SA + k) * 2u);
            bf[2 * bt][0] = r[0]; bf[2 * bt][1] = r[1];
            bf[2 * bt + 1][0] = r[2]; bf[2 * bt + 1][1] = r[3];
        }
        #pragma unroll
        for (int mt = 0; mt < 4; mt++)
            #pragma unroll
            for (int nt = 0; nt < 4; nt++)
                mma_16816(acc[mt][nt], af[mt], bf[nt]);
    }

    // fused epilogue from register accumulators
    const float wbase = g_wbase;
    const int L = g_last;
    const float ic0 = g_invcnt[0], ic1 = g_invcnt[1], ic2 = g_invcnt[2], ic3 = g_invcnt[3];
    const int g = lid >> 2;
    const int t4 = lid & 3;

    float local = 0.f;
    #pragma unroll
    for (int mt = 0; mt < 4; mt++) {
        #pragma unroll
        for (int rh = 0; rh < 2; rh++) {           // acc pair (c0,c1) vs (c2,c3)
            const int ri = rbase + mt * 16 + g + rh * 8;
            const int gi = row0 + ri;
            const int ta = tA[ri];
            const float ica = (ta == 0) ? ic0 : (ta == 1) ? ic1 : (ta == 2) ? ic2 : ic3;
            const bool aL = (ta == L);
            #pragma unroll
            for (int nt = 0; nt < 4; nt++) {
                #pragma unroll
                for (int cc = 0; cc < 2; cc++) {
                    const int cj = cbase + nt * 8 + 2 * t4 + cc;
                    const int gj = col0 + cj;
                    if (gj > gi) {
                        const float cs = acc[mt][nt][rh * 2 + cc];
                        const int tb = tB[cj];
                        const float icb = (tb == 0) ? ic0 : (tb == 1) ? ic1 : (tb == 2) ? ic2 : ic3;
                        const float w = (ta == tb) ? wbase : (wbase - ica - icb);
                        local += w * (1.0f - cs);
                        if (aL != (tb == L)) local += fmaxf(cs - 0.5f, 0.0f);
                    }
                }
            }
        }
    }

    // reduce
    #pragma unroll
    for (int o = 16; o > 0; o >>= 1) local += __shfl_xor_sync(0xffffffffu, local, o);
    float* red = (float*)(smem + OFF_RED);
    if (lid == 0) red[wid] = local;
    __syncthreads();
    if (tid == 0) {
        float z = 0.f;
        #pragma unroll
        for (int i = 0; i < 8; i++) z += red[i];
        atomicAdd(&g_sum, (double)z);
    }
}

// ---------------- finalize ----------------
__global__ void finalize_kernel(float* out, double invN) {
    out[0] = (float)(g_sum * invN);
}

extern "C" void kernel_launch(void* const* d_in, const int* in_sizes, int n_in,
                              void* d_out, int out_size) {
    const float* x = (const float*)d_in[0];
    const int* traw = (const int*)d_in[1];
    float* out = (float*)d_out;

    const int n = in_sizes[1];
    const int nTiles = n / TILE;
    const int nBlocks = nTiles * (nTiles + 1) / 2;

    cudaFuncSetAttribute(pair_kernel, cudaFuncAttributeMaxDynamicSharedMemorySize, SMEM_TOTAL);

    setup_kernel<<<1, 256>>>(traw, n);
    normalize_kernel<<<n, E_DIM>>>(x);
    pair_kernel<<<nBlocks, 256, SMEM_TOTAL>>>(nTiles);
    finalize_kernel<<<1, 1>>>(out, 1.0 / (double)n);
}

// round 6
// speedup vs baseline: 3.8814x; 1.5621x over previous
#include <cuda_runtime.h>
#include <cuda_bf16.h>
#include <math.h>
#include <stdint.h>

#define E_DIM 256
#define N_MAX 8192
#define TILE 128
#define CHUNK 64
#define NCHUNK (E_DIM / CHUNK)      // 4
#define SAW 72                       // smem row stride in bf16 (144B): 4-bank skew, ldmatrix conflict-free
#define STAGE_BYTES (TILE * SAW * 2) // 18432

// ---------------- device scratch ----------------
__device__ __nv_bfloat16 g_xb[N_MAX * E_DIM];
__device__ int      g_target[N_MAX];
__device__ float    g_invcnt[4];
__device__ float    g_wbase;
__device__ int      g_last;
__device__ double   g_sum;
__device__ unsigned g_done;

// ---------------- helpers ----------------
__device__ __forceinline__ uint32_t smem_u32(const void* p) {
    uint32_t a;
    asm("{ .reg .u64 t; cvta.to.shared.u64 t, %1; cvt.u32.u64 %0, t; }" : "=r"(a) : "l"(p));
    return a;
}
__device__ __forceinline__ void cp_async16(uint32_t dst, const void* src) {
    asm volatile("cp.async.cg.shared.global [%0], [%1], 16;" :: "r"(dst), "l"(src) : "memory");
}
__device__ __forceinline__ void cp_commit() {
    asm volatile("cp.async.commit_group;" ::: "memory");
}
__device__ __forceinline__ void cp_wait1() {
    asm volatile("cp.async.wait_group 1;" ::: "memory");
}
__device__ __forceinline__ void cp_wait0() {
    asm volatile("cp.async.wait_group 0;" ::: "memory");
}
__device__ __forceinline__ void ldsm_x4(uint32_t* r, uint32_t addr) {
    asm volatile("ldmatrix.sync.aligned.m8n8.x4.shared.b16 {%0,%1,%2,%3}, [%4];"
                 : "=r"(r[0]), "=r"(r[1]), "=r"(r[2]), "=r"(r[3]) : "r"(addr));
}
__device__ __forceinline__ void mma_16816(float* d, const uint32_t* a, const uint32_t* b) {
    asm volatile(
        "mma.sync.aligned.m16n8k16.row.col.f32.bf16.bf16.f32 "
        "{%0,%1,%2,%3}, {%4,%5,%6,%7}, {%8,%9}, {%0,%1,%2,%3};"
        : "+f"(d[0]), "+f"(d[1]), "+f"(d[2]), "+f"(d[3])
        : "r"(a[0]), "r"(a[1]), "r"(a[2]), "r"(a[3]), "r"(b[0]), "r"(b[1]));
}

// ---------------- prep: normalize rows + (block 0) target setup ----------------
__global__ void prep_kernel(const float* __restrict__ x, const int* __restrict__ traw, int n) {
    const int row = blockIdx.x;
    const int t = threadIdx.x;

    // normalize this row
    float v = x[row * E_DIM + t];
    float s = v * v;
    #pragma unroll
    for (int o = 16; o > 0; o >>= 1) s += __shfl_xor_sync(0xffffffffu, s, o);
    __shared__ float ws[8];
    __shared__ float s_inv;
    if ((t & 31) == 0) ws[t >> 5] = s;
    __syncthreads();
    if (t == 0) {
        float z = 0.f;
        #pragma unroll
        for (int i = 0; i < 8; i++) z += ws[i];
        s_inv = 1.0f / fmaxf(sqrtf(z), 1e-8f);
    }
    __syncthreads();
    g_xb[row * E_DIM + t] = __float2bfloat16(v * s_inv);

    // block 0: target decode + histogram + constants + accumulator reset
    if (row == 0) {
        __shared__ int s_cnt[4];
        __shared__ int s_flag;
        if (t < 4) s_cnt[t] = 0;
        if (t == 0) { s_flag = 0; g_sum = 0.0; g_done = 0u; }
        __syncthreads();
        int f = 0;
        for (int i = 2 * t + 1; i < n; i += 2 * blockDim.x)
            if (traw[i] != 0) f = 1;
        if (f) atomicOr(&s_flag, 1);
        __syncthreads();
        const int is64 = (s_flag == 0);
        for (int i = t; i < n; i += blockDim.x) {
            int tv = is64 ? traw[2 * i] : traw[i];
            g_target[i] = tv;
            atomicAdd(&s_cnt[tv & 3], 1);
        }
        __syncthreads();
        if (t == 0) {
            float wb = 0.f;
            int L = 0;
            for (int c = 0; c < 4; c++) {
                float ic = (s_cnt[c] > 0) ? (1.0f / (float)s_cnt[c]) : 0.0f;
                g_invcnt[c] = ic;
                if (s_cnt[c] > 0) { wb += ic; L = c; }
            }
            g_wbase = wb;
            g_last = L;
        }
    }
}

// ---------------- pair kernel ----------------
#define OFF_TA   0
#define OFF_TB   512
#define OFF_RED  1024
#define OFF_A    1536
#define OFF_B    (OFF_A + 2 * STAGE_BYTES)
#define SMEM_TOTAL (OFF_B + 2 * STAGE_BYTES)

__global__ __launch_bounds__(256, 2) void pair_kernel(float* __restrict__ out,
                                                      int nTiles, int nBlocks, float invN) {
    extern __shared__ char smem[];
    const uint32_t sbase = smem_u32(smem);
    const int tid = threadIdx.x;
    const int wid = tid >> 5;
    const int lid = tid & 31;

    // block -> (bi, bj), bj >= bi
    int idx = blockIdx.x;
    int bi = 0;
    while (idx >= nTiles - bi) { idx -= nTiles - bi; bi++; }
    const int bj = bi + idx;
    const int row0 = bi * TILE;
    const int col0 = bj * TILE;

    const uint4* __restrict__ srcA = (const uint4*)(g_xb + (size_t)row0 * E_DIM);
    const uint4* __restrict__ srcB = (const uint4*)(g_xb + (size_t)col0 * E_DIM);

    // chunk loader: 128 rows x 64 cols (8 uint4 per row) per tile, both tiles
    auto load_chunk = [&](int c, int stage) {
        const uint32_t dA = sbase + OFF_A + stage * STAGE_BYTES;
        const uint32_t dB = sbase + OFF_B + stage * STAGE_BYTES;
        #pragma unroll
        for (int it = 0; it < 4; it++) {
            int v = tid + it * 256;          // 0..1023
            int row = v >> 3;
            int q = v & 7;
            uint32_t d = (uint32_t)(row * SAW + q * 8) * 2u;
            int gsrc = row * 32 + c * 8 + q;
            cp_async16(dA + d, srcA + gsrc);
            cp_async16(dB + d, srcB + gsrc);
        }
        cp_commit();
    };

    int* tA = (int*)(smem + OFF_TA);
    int* tB = (int*)(smem + OFF_TB);
    if (tid < TILE) { tA[tid] = g_target[row0 + tid]; tB[tid] = g_target[col0 + tid]; }

    load_chunk(0, 0);

    // warp decomposition: wm in {0,1} -> 64 rows, wn in {0..3} -> 32 cols
    const int wm = wid & 1;
    const int wn = wid >> 1;
    const int rbase = wm * 64;
    const int cbase = wn * 32;

    float acc[4][4][4];
    #pragma unroll
    for (int mt = 0; mt < 4; mt++)
        #pragma unroll
        for (int nt = 0; nt < 4; nt++)
            #pragma unroll
            for (int q = 0; q < 4; q++) acc[mt][nt][q] = 0.f;

    const int mi = lid >> 3;
    const int mr = lid & 7;
    // A x4: m0 rows+0 k+0 | m1 rows+8 k+0 | m2 rows+0 k+8 | m3 rows+8 k+8
    const uint32_t aOff = (uint32_t)((rbase + mr + (mi & 1) * 8) * SAW + (mi >> 1) * 8) * 2u;
    // B x4: m0 n+0 k+0 | m1 n+0 k+8 | m2 n+8 k+0 | m3 n+8 k+8
    const uint32_t bOff = (uint32_t)((cbase + mr + (mi >> 1) * 8) * SAW + (mi & 1) * 8) * 2u;

    #pragma unroll
    for (int c = 0; c < NCHUNK; c++) {
        const int stage = c & 1;
        if (c + 1 < NCHUNK) {
            load_chunk(c + 1, (c + 1) & 1);
            cp_wait1();
        } else {
            cp_wait0();
        }
        __syncthreads();

        const uint32_t aBase = sbase + OFF_A + stage * STAGE_BYTES + aOff;
        const uint32_t bBase = sbase + OFF_B + stage * STAGE_BYTES + bOff;

        #pragma unroll
        for (int k = 0; k < CHUNK; k += 16) {
            uint32_t af[4][4];
            uint32_t bf[4][2];
            #pragma unroll
            for (int mt = 0; mt < 4; mt++)
                ldsm_x4(af[mt], aBase + (uint32_t)(mt * 16 * SAW + k) * 2u);
            #pragma unroll
            for (int bt = 0; bt < 2; bt++) {
                uint32_t r[4];
                ldsm_x4(r, bBase + (uint32_t)(bt * 16 * SAW + k) * 2u);
                bf[2 * bt][0] = r[0]; bf[2 * bt][1] = r[1];
                bf[2 * bt + 1][0] = r[2]; bf[2 * bt + 1][1] = r[3];
            }
            #pragma unroll
            for (int mt = 0; mt < 4; mt++)
                #pragma unroll
                for (int nt = 0; nt < 4; nt++)
                    mma_16816(acc[mt][nt], af[mt], bf[nt]);
        }
        __syncthreads();   // protect stage buffer before it is reloaded
    }

    // fused epilogue
    const float wbase = g_wbase;
    const int L = g_last;
    const float ic0 = g_invcnt[0], ic1 = g_invcnt[1], ic2 = g_invcnt[2], ic3 = g_invcnt[3];
    const int g = lid >> 2;
    const int t4 = lid & 3;

    float local = 0.f;
    #pragma unroll
    for (int mt = 0; mt < 4; mt++) {
        #pragma unroll
        for (int rh = 0; rh < 2; rh++) {
            const int ri = rbase + mt * 16 + g + rh * 8;
            const int gi = row0 + ri;
            const int ta = tA[ri];
            const float ica = (ta == 0) ? ic0 : (ta == 1) ? ic1 : (ta == 2) ? ic2 : ic3;
            const bool aL = (ta == L);
            #pragma unroll
            for (int nt = 0; nt < 4; nt++) {
                #pragma unroll
                for (int cc = 0; cc < 2; cc++) {
                    const int cj = cbase + nt * 8 + 2 * t4 + cc;
                    const int gj = col0 + cj;
                    if (gj > gi) {
                        const float cs = acc[mt][nt][rh * 2 + cc];
                        const int tb = tB[cj];
                        const float icb = (tb == 0) ? ic0 : (tb == 1) ? ic1 : (tb == 2) ? ic2 : ic3;
                        const float w = (ta == tb) ? wbase : (wbase - ica - icb);
                        local += w * (1.0f - cs);
                        if (aL != (tb == L)) local += fmaxf(cs - 0.5f, 0.0f);
                    }
                }
            }
        }
    }

    // block reduce
    #pragma unroll
    for (int o = 16; o > 0; o >>= 1) local += __shfl_xor_sync(0xffffffffu, local, o);
    float* red = (float*)(smem + OFF_RED);
    if (lid == 0) red[wid] = local;
    __syncthreads();
    if (tid == 0) {
        float z = 0.f;
        #pragma unroll
        for (int i = 0; i < 8; i++) z += red[i];
        atomicAdd(&g_sum, (double)z);
        __threadfence();
        unsigned done = atomicAdd(&g_done, 1u);
        if (done == (unsigned)(nBlocks - 1)) {
            double total = *(volatile double*)&g_sum;
            out[0] = (float)(total * (double)invN);
        }
    }
}

extern "C" void kernel_launch(void* const* d_in, const int* in_sizes, int n_in,
                              void* d_out, int out_size) {
    const float* x = (const float*)d_in[0];
    const int* traw = (const int*)d_in[1];
    float* out = (float*)d_out;

    const int n = in_sizes[1];
    const int nTiles = n / TILE;
    const int nBlocks = nTiles * (nTiles + 1) / 2;

    cudaFuncSetAttribute(pair_kernel, cudaFuncAttributeMaxDynamicSharedMemorySize, SMEM_TOTAL);

    prep_kernel<<<n, 256>>>(x, traw, n);
    pair_kernel<<<nBlocks, 256, SMEM_TOTAL>>>(out, nTiles, nBlocks, 1.0f / (float)n);
}